// round 10
// baseline (speedup 1.0000x reference)
#include <cuda_runtime.h>
#include <cuda_fp16.h>

// Problem constants (fixed shapes from reference)
#define BS   1024        // B*S = 2*512
#define F    16384
#define D    768
#define M    262144
#define CHUNKS 8         // bs-chunks of 128 in main kernel (BS/128)

// ---------------- scratch (static device globals; no allocation) ----------------
__device__ __align__(16) __half g_BTh [(size_t)F * D];   // up_decoder^T  [F, D]  half
__device__ __align__(16) __half g_upTh[(size_t)F * BS];  // up_facts^T    [F, BS] half
__device__ __align__(16) float  g_vals[M];               // connection values
__device__ int            g_ii  [M];                     // normalized i indices
__device__ unsigned short g_jj  [M];                     // normalized j indices
__device__ int            g_rowptr[F + 1];               // CSR over sorted i
__device__ int            g_mode;                        // 1 = int64 indices, 0 = int32

// ---------------- dtype detection + index normalization -------------------------
__global__ void k_detect(const void* __restrict__ j_raw) {
    if (threadIdx.x == 0 && blockIdx.x == 0) {
        const long long* p = (const long long*)j_raw;
        int ok = 1;
        for (int t = 0; t < 64; t++) {
            long long v = p[t];
            if (v < 0 || v >= F) { ok = 0; break; }
        }
        g_mode = ok;
    }
}

__global__ void k_decode(const void* __restrict__ i_raw, const void* __restrict__ j_raw) {
    int m = blockIdx.x * blockDim.x + threadIdx.x;
    if (m >= M) return;
    int iv, jv;
    if (g_mode) {
        iv = (int)((const long long*)i_raw)[m];
        jv = (int)((const long long*)j_raw)[m];
    } else {
        iv = ((const int*)i_raw)[m];
        jv = ((const int*)j_raw)[m];
    }
    g_ii[m] = iv;
    g_jj[m] = (unsigned short)jv;
}

// ---------------- build CSR row_ptr from sorted g_ii -----------------------------
__global__ void k_build() {
    int m = blockIdx.x * blockDim.x + threadIdx.x;
    if (m < M) {
        int cur  = g_ii[m];
        int prev = (m == 0) ? -1 : g_ii[m - 1];
        for (int f = prev + 1; f <= cur; f++) g_rowptr[f] = m;
    } else if (m == M) {
        int last = g_ii[M - 1];
        for (int f = last + 1; f <= F; f++) g_rowptr[f] = M;
    }
}

// ------------- tiled transpose fp32 [R,C] -> half [C,R] --------------------------
template<int R, int C>
__device__ __forceinline__ void transpose_h_body(const float* __restrict__ in,
                                                 __half* __restrict__ out) {
    __shared__ float tile[32][33];
    int cx = blockIdx.x * 32 + threadIdx.x;   // col in input
    int ry = blockIdx.y * 32 + threadIdx.y;   // row in input
#pragma unroll
    for (int k = 0; k < 32; k += 8)
        tile[threadIdx.y + k][threadIdx.x] = in[(size_t)(ry + k) * C + cx];
    __syncthreads();
    int ox = blockIdx.y * 32 + threadIdx.x;
    int oy = blockIdx.x * 32 + threadIdx.y;
#pragma unroll
    for (int k = 0; k < 32; k += 8)
        out[(size_t)(oy + k) * R + ox] = __float2half_rn(tile[threadIdx.x][threadIdx.y + k]);
}

__global__ void k_t_updec(const float* __restrict__ in) { transpose_h_body<D,  F >(in, g_BTh);  }
__global__ void k_t_upfac(const float* __restrict__ in) { transpose_h_body<BS, F >(in, g_upTh); }

// -------- values: block per feature i; de[i] row staged in smem ------------------
// Each of the ~16 connections in CSR row i re-uses the smem copy of de[i],
// eliminating the 16x re-fetch of the 3KB row from L2 (0.79 GB -> 0.05 GB).
__global__ void __launch_bounds__(256) k_values(const float* __restrict__ de) {
    int i = blockIdx.x;
    int start = g_rowptr[i];
    int end   = g_rowptr[i + 1];
    if (start == end) return;

    __shared__ float sde[D];
    for (int t = threadIdx.x; t < D; t += 256)
        sde[t] = de[(size_t)i * D + t];
    __syncthreads();

    int warp = threadIdx.x >> 5;
    int lane = threadIdx.x & 31;
    const float2* sde2 = (const float2*)sde;   // 384 float2, conflict-free lane stride

    for (int m = start + warp; m < end; m += 8) {
        int j = (int)g_jj[m];
        const half2* b = (const half2*)(g_BTh + (size_t)j * D);   // 384 half2
        float acc = 0.f;
#pragma unroll
        for (int k = 0; k < (D / 2) / 32; k++) {   // 12 iterations
            float2 bv = __half22float2(b[lane + 32 * k]);
            float2 av = sde2[lane + 32 * k];
            acc += av.x * bv.x + av.y * bv.y;
        }
#pragma unroll
        for (int off = 16; off; off >>= 1) acc += __shfl_xor_sync(0xffffffffu, acc, off);
        if (lane == 0) g_vals[m] = acc;
    }
}

// ------ main: block = 32 features x 128-bs chunk; CSR reduce; SMEM transpose -----
// Inner loop unrolled x4: four independent LDG.64s in flight per step.
__global__ void __launch_bounds__(1024) k_main(float* __restrict__ out) {
    int warp = threadIdx.x >> 5;         // 0..31: feature offset within block
    int lane = threadIdx.x & 31;
    int i_base = blockIdx.x * 32;
    int chunk  = blockIdx.y;             // 0..CHUNKS-1
    int i = i_base + warp;

    int start = g_rowptr[i];
    int end   = g_rowptr[i + 1];

    const uint2* uph = (const uint2*)g_upTh;       // 4 halfs per uint2; row = BS/4 = 256
    int base4 = chunk * 32 + lane;                 // uint2 index within a row

    float4 acc = make_float4(0.f, 0.f, 0.f, 0.f);
    for (int s0 = start; s0 < end; s0 += 32) {
        int idx = s0 + lane;
        int   jv = 0;
        float vv = 0.f;
        if (idx < end) { jv = (int)g_jj[idx]; vv = g_vals[idx]; }
        int n = min(32, end - s0);
        int t = 0;
        for (; t + 4 <= n; t += 4) {
            int   j0 = __shfl_sync(0xffffffffu, jv, t + 0);
            int   j1 = __shfl_sync(0xffffffffu, jv, t + 1);
            int   j2 = __shfl_sync(0xffffffffu, jv, t + 2);
            int   j3 = __shfl_sync(0xffffffffu, jv, t + 3);
            float v0 = __shfl_sync(0xffffffffu, vv, t + 0);
            float v1 = __shfl_sync(0xffffffffu, vv, t + 1);
            float v2 = __shfl_sync(0xffffffffu, vv, t + 2);
            float v3 = __shfl_sync(0xffffffffu, vv, t + 3);
            uint2 r0 = uph[(size_t)j0 * (BS / 4) + base4];
            uint2 r1 = uph[(size_t)j1 * (BS / 4) + base4];
            uint2 r2 = uph[(size_t)j2 * (BS / 4) + base4];
            uint2 r3 = uph[(size_t)j3 * (BS / 4) + base4];
            float2 a0 = __half22float2(*(const half2*)&r0.x);
            float2 b0 = __half22float2(*(const half2*)&r0.y);
            acc.x += v0 * a0.x; acc.y += v0 * a0.y; acc.z += v0 * b0.x; acc.w += v0 * b0.y;
            float2 a1 = __half22float2(*(const half2*)&r1.x);
            float2 b1 = __half22float2(*(const half2*)&r1.y);
            acc.x += v1 * a1.x; acc.y += v1 * a1.y; acc.z += v1 * b1.x; acc.w += v1 * b1.y;
            float2 a2 = __half22float2(*(const half2*)&r2.x);
            float2 b2 = __half22float2(*(const half2*)&r2.y);
            acc.x += v2 * a2.x; acc.y += v2 * a2.y; acc.z += v2 * b2.x; acc.w += v2 * b2.y;
            float2 a3 = __half22float2(*(const half2*)&r3.x);
            float2 b3 = __half22float2(*(const half2*)&r3.y);
            acc.x += v3 * a3.x; acc.y += v3 * a3.y; acc.z += v3 * b3.x; acc.w += v3 * b3.y;
        }
        for (; t < n; t++) {
            int   jt = __shfl_sync(0xffffffffu, jv, t);
            float vt = __shfl_sync(0xffffffffu, vv, t);
            uint2 raw = uph[(size_t)jt * (BS / 4) + base4];
            float2 f0 = __half22float2(*(const half2*)&raw.x);
            float2 f1 = __half22float2(*(const half2*)&raw.y);
            acc.x += vt * f0.x; acc.y += vt * f0.y;
            acc.z += vt * f1.x; acc.w += vt * f1.y;
        }
    }

    // Block transpose: sm[feature][bs_local], padded to kill bank conflicts.
    __shared__ float sm[32][129];
    int b0i = lane * 4;
    sm[warp][b0i + 0] = acc.x;
    sm[warp][b0i + 1] = acc.y;
    sm[warp][b0i + 2] = acc.z;
    sm[warp][b0i + 3] = acc.w;
    __syncthreads();

#pragma unroll
    for (int r = 0; r < 4; r++) {
        int bs_local = warp * 4 + r;               // 32 warps x 4 rows = 128 bs rows
        int bs = chunk * 128 + bs_local;
        out[(size_t)bs * F + i_base + lane] = sm[lane][bs_local];  // 128B coalesced
    }
}

// ---------------- launch (fork-join stream capture for overlap) ------------------
extern "C" void kernel_launch(void* const* d_in, const int* in_sizes, int n_in,
                              void* d_out, int out_size) {
    const float* up_facts = (const float*)d_in[0];     // [BS, F]
    const float* down_enc = (const float*)d_in[1];     // [F, D]
    const float* up_dec   = (const float*)d_in[2];     // [D, F]
    const void*  i_raw    = d_in[3];                   // [M] sorted (int32 or int64)
    const void*  j_raw    = d_in[4];                   // [M]
    float*       out      = (float*)d_out;             // [BS, F]

    // One-time host resource creation (no device memory involved).
    static cudaStream_t s1 = nullptr, s2 = nullptr;
    static cudaEvent_t  e0, eDec, eVals, eUpfac;
    if (s1 == nullptr) {
        cudaStreamCreateWithFlags(&s1, cudaStreamNonBlocking);
        cudaStreamCreateWithFlags(&s2, cudaStreamNonBlocking);
        cudaEventCreateWithFlags(&e0,     cudaEventDisableTiming);
        cudaEventCreateWithFlags(&eDec,   cudaEventDisableTiming);
        cudaEventCreateWithFlags(&eVals,  cudaEventDisableTiming);
        cudaEventCreateWithFlags(&eUpfac, cudaEventDisableTiming);
    }
    cudaStream_t s0 = (cudaStream_t)0;   // legacy default stream (captured)

    dim3 tb(32, 8);
    // Fork: transposes on side streams, index pipeline on s0.
    cudaEventRecord(e0, s0);
    cudaStreamWaitEvent(s1, e0, 0);
    cudaStreamWaitEvent(s2, e0, 0);

    k_t_updec<<<dim3(F / 32, D  / 32), tb, 0, s1>>>(up_dec);    // -> g_BTh
    k_t_upfac<<<dim3(F / 32, BS / 32), tb, 0, s2>>>(up_facts);  // -> g_upTh
    cudaEventRecord(eUpfac, s2);

    k_detect <<<1, 32, 0, s0>>>(j_raw);
    k_decode <<<(M + 255) / 256, 256, 0, s0>>>(i_raw, j_raw);   // -> g_ii, g_jj
    k_build  <<<(M + 256) / 256, 256, 0, s0>>>();               // -> g_rowptr
    cudaEventRecord(eDec, s0);

    // values needs {decode, build, t_updec}: run on s1 after eDec.
    cudaStreamWaitEvent(s1, eDec, 0);
    k_values <<<F, 256, 0, s1>>>(down_enc);                     // -> g_vals
    cudaEventRecord(eVals, s1);

    // main needs {build (s0), values (s1), t_upfac (s2)}.
    cudaStreamWaitEvent(s0, eVals, 0);
    cudaStreamWaitEvent(s0, eUpfac, 0);
    k_main   <<<dim3(F / 32, CHUNKS), 1024, 0, s0>>>(out);      // -> d_out directly
}

// round 12
// speedup vs baseline: 1.0948x; 1.0948x over previous
#include <cuda_runtime.h>
#include <cuda_fp16.h>

// Problem constants (fixed shapes from reference)
#define BS   1024        // B*S = 2*512
#define F    16384
#define D    768
#define M    262144
#define CHUNKS 8         // bs-chunks of 128 in main kernel (BS/128)
#define MLO  147456      // M/2 + 16384 (64-sigma safe split point)

// ---------------- scratch (static device globals; no allocation) ----------------
__device__ __align__(16) __half g_BTh [(size_t)F * D];   // up_decoder^T  [F, D]  half
__device__ __align__(16) __half g_upTh[(size_t)F * BS];  // up_facts^T    [F, BS] half
__device__ __align__(16) float  g_vals[M];               // connection values
__device__ int            g_ii  [M];                     // normalized i indices
__device__ unsigned short g_jj  [M];                     // normalized j indices
__device__ int            g_rowptr[F + 1];               // CSR over sorted i
__device__ int            g_mode;                        // 1 = int64 indices, 0 = int32

// ---------------- dtype detection + index normalization -------------------------
__global__ void k_detect(const void* __restrict__ j_raw) {
    if (threadIdx.x == 0 && blockIdx.x == 0) {
        const long long* p = (const long long*)j_raw;
        int ok = 1;
        for (int t = 0; t < 64; t++) {
            long long v = p[t];
            if (v < 0 || v >= F) { ok = 0; break; }
        }
        g_mode = ok;
    }
}

__global__ void k_decode(const void* __restrict__ i_raw, const void* __restrict__ j_raw) {
    int m = blockIdx.x * blockDim.x + threadIdx.x;
    if (m >= M) return;
    int iv, jv;
    if (g_mode) {
        iv = (int)((const long long*)i_raw)[m];
        jv = (int)((const long long*)j_raw)[m];
    } else {
        iv = ((const int*)i_raw)[m];
        jv = ((const int*)j_raw)[m];
    }
    g_ii[m] = iv;
    g_jj[m] = (unsigned short)jv;
}

// ---------------- build CSR row_ptr from sorted g_ii -----------------------------
__global__ void k_build() {
    int m = blockIdx.x * blockDim.x + threadIdx.x;
    if (m < M) {
        int cur  = g_ii[m];
        int prev = (m == 0) ? -1 : g_ii[m - 1];
        for (int f = prev + 1; f <= cur; f++) g_rowptr[f] = m;
    } else if (m == M) {
        int last = g_ii[M - 1];
        for (int f = last + 1; f <= F; f++) g_rowptr[f] = M;
    }
}

// ------------- tiled transpose fp32 [R,C] -> half [C,R] --------------------------
template<int R, int C>
__device__ __forceinline__ void transpose_h_body(const float* __restrict__ in,
                                                 __half* __restrict__ out) {
    __shared__ float tile[32][33];
    int cx = blockIdx.x * 32 + threadIdx.x;   // col in input
    int ry = blockIdx.y * 32 + threadIdx.y;   // row in input
#pragma unroll
    for (int k = 0; k < 32; k += 8)
        tile[threadIdx.y + k][threadIdx.x] = in[(size_t)(ry + k) * C + cx];
    __syncthreads();
    int ox = blockIdx.y * 32 + threadIdx.x;
    int oy = blockIdx.x * 32 + threadIdx.y;
#pragma unroll
    for (int k = 0; k < 32; k += 8)
        out[(size_t)(oy + k) * R + ox] = __float2half_rn(tile[threadIdx.x][threadIdx.y + k]);
}

__global__ void k_t_updec(const float* __restrict__ in) { transpose_h_body<D,  F >(in, g_BTh);  }
__global__ void k_t_upfac(const float* __restrict__ in) { transpose_h_body<BS, F >(in, g_upTh); }

// -------- values[m] = <down_enc[i_m,:], BTh[j_m,:]> ; warp per m -----------------
// Sorted i => the ~16 warps sharing an i mostly share a block => de row L1-hot.
// Vectorized: float4 de + uint2 (4 halfs) BTh, 6 lane-strided iterations.
__global__ void k_values(const float* __restrict__ de, int m0) {
    int w    = m0 + ((blockIdx.x * blockDim.x + threadIdx.x) >> 5);
    int lane = threadIdx.x & 31;
    int i = __ldg(&g_ii[w]);
    int j = (int)__ldg(&g_jj[w]);
    const float4* a = (const float4*)(de + (size_t)i * D);     // 192 float4
    const uint2*  b = (const uint2*)(g_BTh + (size_t)j * D);   // 192 uint2 (4 halfs)
    float4 acc = make_float4(0.f, 0.f, 0.f, 0.f);
#pragma unroll
    for (int k = 0; k < (D / 4) / 32; k++) {        // 6 iterations
        float4 av = a[lane + 32 * k];
        uint2  bw = b[lane + 32 * k];
        float2 b0 = __half22float2(*(const half2*)&bw.x);
        float2 b1 = __half22float2(*(const half2*)&bw.y);
        acc.x += av.x * b0.x; acc.y += av.y * b0.y;
        acc.z += av.z * b1.x; acc.w += av.w * b1.y;
    }
    float s = (acc.x + acc.y) + (acc.z + acc.w);
#pragma unroll
    for (int off = 16; off; off >>= 1) s += __shfl_xor_sync(0xffffffffu, s, off);
    if (lane == 0) g_vals[w] = s;
}

// ------ main: block = 32 features x 128-bs chunk; CSR reduce; SMEM transpose -----
// i_off selects the feature half (0 or F/64 block-columns).
__global__ void __launch_bounds__(1024) k_main(float* __restrict__ out, int i_off) {
    int warp = threadIdx.x >> 5;         // 0..31: feature offset within block
    int lane = threadIdx.x & 31;
    int i_base = (blockIdx.x + i_off) * 32;
    int chunk  = blockIdx.y;             // 0..CHUNKS-1
    int i = i_base + warp;

    int start = g_rowptr[i];
    int end   = g_rowptr[i + 1];

    const uint2* uph = (const uint2*)g_upTh;       // 4 halfs per uint2; row = BS/4 = 256
    int base4 = chunk * 32 + lane;                 // uint2 index within a row

    float4 acc = make_float4(0.f, 0.f, 0.f, 0.f);
    for (int s0 = start; s0 < end; s0 += 32) {
        int idx = s0 + lane;
        int   jv = 0;
        float vv = 0.f;
        if (idx < end) { jv = (int)g_jj[idx]; vv = g_vals[idx]; }
        int n = min(32, end - s0);
        for (int t = 0; t < n; t++) {
            int   jt = __shfl_sync(0xffffffffu, jv, t);
            float vt = __shfl_sync(0xffffffffu, vv, t);
            uint2 raw = uph[(size_t)jt * (BS / 4) + base4];   // 256B/warp coalesced
            float2 f0 = __half22float2(*(const half2*)&raw.x);
            float2 f1 = __half22float2(*(const half2*)&raw.y);
            acc.x += vt * f0.x; acc.y += vt * f0.y;
            acc.z += vt * f1.x; acc.w += vt * f1.y;
        }
    }

    // Block transpose: sm[feature][bs_local], padded to kill read bank conflicts.
    __shared__ float sm[32][129];
    int b0i = lane * 4;
    sm[warp][b0i + 0] = acc.x;
    sm[warp][b0i + 1] = acc.y;
    sm[warp][b0i + 2] = acc.z;
    sm[warp][b0i + 3] = acc.w;
    __syncthreads();

#pragma unroll
    for (int r = 0; r < 4; r++) {
        int bs_local = warp * 4 + r;               // 32 warps x 4 rows = 128 bs rows
        int bs = chunk * 128 + bs_local;
        out[(size_t)bs * F + i_base + lane] = sm[lane][bs_local];  // 128B coalesced
    }
}

// ---------------- launch (fork-join + values/main pipelining) --------------------
extern "C" void kernel_launch(void* const* d_in, const int* in_sizes, int n_in,
                              void* d_out, int out_size) {
    const float* up_facts = (const float*)d_in[0];     // [BS, F]
    const float* down_enc = (const float*)d_in[1];     // [F, D]
    const float* up_dec   = (const float*)d_in[2];     // [D, F]
    const void*  i_raw    = d_in[3];                   // [M] sorted (int32 or int64)
    const void*  j_raw    = d_in[4];                   // [M]
    float*       out      = (float*)d_out;             // [BS, F]

    // One-time host resource creation (no device memory involved).
    static cudaStream_t s1 = nullptr, s2 = nullptr;
    static cudaEvent_t  e0, eDec, eVlo, eVhi, eUpfac;
    if (s1 == nullptr) {
        cudaStreamCreateWithFlags(&s1, cudaStreamNonBlocking);
        cudaStreamCreateWithFlags(&s2, cudaStreamNonBlocking);
        cudaEventCreateWithFlags(&e0,     cudaEventDisableTiming);
        cudaEventCreateWithFlags(&eDec,   cudaEventDisableTiming);
        cudaEventCreateWithFlags(&eVlo,   cudaEventDisableTiming);
        cudaEventCreateWithFlags(&eVhi,   cudaEventDisableTiming);
        cudaEventCreateWithFlags(&eUpfac, cudaEventDisableTiming);
    }
    cudaStream_t s0 = (cudaStream_t)0;   // legacy default stream (captured)

    dim3 tb(32, 8);
    // Fork: transposes on side streams, index pipeline on s0.
    cudaEventRecord(e0, s0);
    cudaStreamWaitEvent(s1, e0, 0);
    cudaStreamWaitEvent(s2, e0, 0);

    k_t_updec<<<dim3(F / 32, D  / 32), tb, 0, s1>>>(up_dec);    // -> g_BTh
    k_t_upfac<<<dim3(F / 32, BS / 32), tb, 0, s2>>>(up_facts);  // -> g_upTh
    cudaEventRecord(eUpfac, s2);

    k_detect <<<1, 32, 0, s0>>>(j_raw);
    k_decode <<<(M + 255) / 256, 256, 0, s0>>>(i_raw, j_raw);   // -> g_ii, g_jj
    k_build  <<<(M + 256) / 256, 256, 0, s0>>>();               // -> g_rowptr
    cudaEventRecord(eDec, s0);

    // values on s1 (after t_updec in-stream and eDec): split lo/hi for pipelining.
    cudaStreamWaitEvent(s1, eDec, 0);
    k_values <<<MLO / 8, 256, 0, s1>>>(down_enc, 0);            // m in [0, MLO)
    cudaEventRecord(eVlo, s1);
    k_values <<<(M - MLO) / 8, 256, 0, s1>>>(down_enc, MLO);    // m in [MLO, M)
    cudaEventRecord(eVhi, s1);

    // main_lo (features [0, F/2)) needs values_lo + t_upfac; overlaps values_hi.
    cudaStreamWaitEvent(s0, eVlo, 0);
    cudaStreamWaitEvent(s0, eUpfac, 0);
    k_main   <<<dim3(F / 64, CHUNKS), 1024, 0, s0>>>(out, 0);
    // main_hi (features [F/2, F)) needs all values.
    cudaStreamWaitEvent(s0, eVhi, 0);
    k_main   <<<dim3(F / 64, CHUNKS), 1024, 0, s0>>>(out, F / 64);
}